// round 15
// baseline (speedup 1.0000x reference)
#include <cuda_runtime.h>
#include <cuda_fp16.h>
#include <math.h>
#include <stdint.h>

#define Bn 8
#define HWn 4096
#define Dn 256
#define LWn 1024
#define NWn 32
#define DHn 2048
#define Mtot (Bn*HWn)

// ---------------- scratch (device globals; allocation is forbidden) --------
#define AL16 __align__(16)
__device__ AL16 __half g_src[Mtot*Dn];
__device__ AL16 __half g_tgt[Mtot*Dn];
__device__ AL16 __half g_wq[Dn*Dn], g_wk[Dn*Dn], g_wv[Dn*Dn], g_wm[Dn*Dn];
__device__ AL16 __half g_w1[DHn*2*Dn];
__device__ AL16 __half g_w2[Dn*DHn];
__device__ AL16 __half g_q[Mtot*Dn], g_k[Mtot*Dn], g_vt[Mtot*Dn];
__device__ AL16 __half g_msg[Mtot*Dn];
__device__ AL16 __half g_msgn[Mtot*Dn];
__device__ AL16 __half g_hid[(size_t)Mtot*DHn];

// ---------------- portable PTX helpers (sm_80+ class only) -----------------
__device__ __forceinline__ uint32_t smem_u32(const void* p) {
    uint32_t a;
    asm("{ .reg .u64 t; cvta.to.shared.u64 t, %1; cvt.u32.u64 %0, t; }" : "=r"(a) : "l"(p));
    return a;
}
#define SWZ(o) ((o) ^ (((o) >> 3) & 0x70))

#define CP16(dst, src) asm volatile("cp.async.cg.shared.global [%0],[%1],16;" \
    :: "r"(dst), "l"(__cvta_generic_to_global(src)) : "memory")
#define CP_COMMIT() asm volatile("cp.async.commit_group;" ::: "memory")
#define CP_WAIT1()  asm volatile("cp.async.wait_group 1;" ::: "memory")
#define CP_WAIT0()  asm volatile("cp.async.wait_group 0;" ::: "memory")

#define LDMX4(r, a) asm volatile("ldmatrix.sync.aligned.m8n8.x4.shared.b16 {%0,%1,%2,%3},[%4];" \
    : "=r"((r)[0]), "=r"((r)[1]), "=r"((r)[2]), "=r"((r)[3]) : "r"(a))
#define LDMX2(r, a) asm volatile("ldmatrix.sync.aligned.m8n8.x2.shared.b16 {%0,%1},[%2];" \
    : "=r"((r)[0]), "=r"((r)[1]) : "r"(a))

#define MMA(d, a, b) asm volatile( \
    "mma.sync.aligned.m16n8k16.row.col.f32.f16.f16.f32 " \
    "{%0,%1,%2,%3},{%4,%5,%6,%7},{%8,%9},{%0,%1,%2,%3};" \
    : "+f"((d)[0]), "+f"((d)[1]), "+f"((d)[2]), "+f"((d)[3]) \
    : "r"((a)[0]), "r"((a)[1]), "r"((a)[2]), "r"((a)[3]), "r"((b)[0]), "r"((b)[1]))

// window-token permutation: roll(-16,-16) + 2x2 window split
__device__ __forceinline__ int win_tok(int wi, int l) {
    int i = l >> 5, j = l & 31;
    int y = (((wi >> 1) << 5) + i + 16) & 63;
    int x = (((wi &  1) << 5) + j + 16) & 63;
    return (y << 6) | x;
}

// ---------------- merged fp32 -> fp16 conversion (one launch) ---------------
struct CvtP {
    const float2* in[8];
    __half2* out[8];
    int end[8];
};
__global__ void cvt_all_kernel(CvtP p)
{
    int i = blockIdx.x * 256 + threadIdx.x;
    if (i >= p.end[7]) return;
    int s = 0;
    #pragma unroll
    for (int j = 0; j < 7; j++) s += (i >= p.end[j]);
    int base = (s == 0) ? 0 : p.end[s - 1];
    p.out[s][i - base] = __float22half2_rn(p.in[s][i - base]);
}

// ======================================================================
// Fused window attention v5 (R11/R12 — known good, protected)
// ======================================================================
#define PSTR    1032
#define OFF_P   0
#define OFF_KV  66048
#define KB32    16896
#define VB32    20480
#define OFF_SS  107008
#define OFF_FIS 107520
#define FLASH_SMEM 107648

__global__ void __launch_bounds__(256, 2)
flash_kernel(const __half* __restrict__ q, const __half* __restrict__ k,
             const __half* __restrict__ vt, const float* __restrict__ mask,
             __half* __restrict__ msg)
{
    extern __shared__ char sm[];
    uint32_t sb = smem_u32(sm);
    const int tid = threadIdx.x, wid = tid >> 5, lane = tid & 31;
    const int wgm = wid >> 2, wgn = wid & 3;
    const int m0 = blockIdx.x * 32;
    const int bw = blockIdx.y, b = bw >> 2, wi = bw & 3;
    const float* maskw = mask + (size_t)wi * LWn * LWn;

    #pragma unroll
    for (int it = 0; it < 4; it++) {
        int idx = tid + it * 256, row = idx >> 5, seg = idx & 31;
        const __half* src = q + ((size_t)b * HWn + win_tok(wi, m0 + row)) * Dn + seg * 8;
        CP16(sb + OFF_KV + row * 528 + seg * 16, src);
    }
    CP_COMMIT(); CP_WAIT0(); __syncthreads();
    uint32_t af[16][4];
    {
        int qrow = wgm * 16 + (lane & 15);
        #pragma unroll
        for (int kf = 0; kf < 16; kf++)
            LDMX4(af[kf], sb + OFF_KV + qrow * 528 + (kf * 16 + (lane >> 4) * 8) * 2);
    }
    __syncthreads();

    const int r0 = wgm * 16 + (lane >> 2);
    float srun0 = 0.f, srun1 = 0.f;

    auto fillK = [&](int ch) {
        uint32_t base = sb + OFF_KV + (ch & 1) * KB32;
        int kc = ch * 32;
        #pragma unroll
        for (int it = 0; it < 4; it++) {
            int idx = tid + it * 256, row = idx >> 5, seg = idx & 31;
            const __half* src = k + ((size_t)b * HWn + win_tok(wi, kc + row)) * Dn + seg * 8;
            CP16(base + row * 528 + seg * 16, src);
        }
        CP_COMMIT();
    };
    fillK(0);
    {
        const int key = wgn * 8 + (lane & 7);
        const int koff = ((lane >> 3) & 1) * 8;
        for (int ch = 0; ch < 32; ch++) {
            if (ch + 1 < 32) { fillK(ch + 1); CP_WAIT1(); } else CP_WAIT0();
            __syncthreads();
            int kc = ch * 32;
            int col = kc + wgn * 8 + (lane & 3) * 2;
            float2 mk0 = *(const float2*)&maskw[(size_t)(m0 + r0) * LWn + col];
            float2 mk1 = *(const float2*)&maskw[(size_t)(m0 + r0 + 8) * LWn + col];
            uint32_t base = sb + OFF_KV + (ch & 1) * KB32;
            float sac[4] = {};
            #pragma unroll
            for (int kf = 0; kf < 16; kf++) {
                uint32_t t2[2];
                LDMX2(t2, base + key * 528 + (kf * 16 + koff) * 2);
                MMA(sac, af[kf], t2);
            }
            float p0 = exp2f(fmaf(sac[0] * 0.0625f + mk0.x, 1.4426950408889634f, -2.8853900817779268f));
            float p1 = exp2f(fmaf(sac[1] * 0.0625f + mk0.y, 1.4426950408889634f, -2.8853900817779268f));
            float p2 = exp2f(fmaf(sac[2] * 0.0625f + mk1.x, 1.4426950408889634f, -2.8853900817779268f));
            float p3 = exp2f(fmaf(sac[3] * 0.0625f + mk1.y, 1.4426950408889634f, -2.8853900817779268f));
            srun0 += p0 + p1;
            srun1 += p2 + p3;
            __half2 h0 = __floats2half2_rn(p0, p1);
            __half2 h1 = __floats2half2_rn(p2, p3);
            *(uint32_t*)(sm + OFF_P + (r0 * PSTR + col) * 2)       = *(uint32_t*)&h0;
            *(uint32_t*)(sm + OFF_P + ((r0 + 8) * PSTR + col) * 2) = *(uint32_t*)&h1;
            __syncthreads();
        }
    }
    #pragma unroll
    for (int off = 1; off <= 2; off <<= 1) {
        srun0 += __shfl_xor_sync(0xffffffff, srun0, off);
        srun1 += __shfl_xor_sync(0xffffffff, srun1, off);
    }
    float* smS = (float*)(sm + OFF_SS);
    if ((lane & 3) == 0) {
        smS[wgn * 32 + r0] = srun0;
        smS[wgn * 32 + r0 + 8] = srun1;
    }
    __syncthreads();
    float* fIS = (float*)(sm + OFF_FIS);
    if (tid < 32) {
        float ss = smS[tid] + smS[32 + tid] + smS[64 + tid] + smS[96 + tid];
        fIS[tid] = 1.f / ss;
    }
    __syncthreads();

    float oac[8][4] = {};
    auto fillV = [&](int ch) {
        uint32_t base = sb + OFF_KV + (ch & 1) * VB32;
        int kc = ch * 32;
        #pragma unroll
        for (int it = 0; it < 4; it++) {
            int idx = tid + it * 256, row = idx >> 2, seg = idx & 3;
            const __half* src = vt + ((size_t)b * Dn + row) * (size_t)HWn + win_tok(wi, kc + seg * 8);
            CP16(base + row * 80 + seg * 16, src);
        }
        CP_COMMIT();
    };
    fillV(0);
    const int prow = wgm * 16 + (lane & 15);
    const uint32_t pbase = sb + OFF_P + prow * (PSTR * 2);
    for (int ch = 0; ch < 32; ch++) {
        if (ch + 1 < 32) { fillV(ch + 1); CP_WAIT1(); } else CP_WAIT0();
        __syncthreads();
        uint32_t base = sb + OFF_KV + (ch & 1) * VB32;
        int kc = ch * 32;
        #pragma unroll
        for (int kf = 0; kf < 2; kf++) {
            uint32_t a2[4];
            LDMX4(a2, pbase + (kc + kf * 16 + (lane >> 4) * 8) * 2);
            #pragma unroll
            for (int g = 0; g < 4; g++) {
                uint32_t t4[4];
                int brow = wgn * 64 + g * 16 + ((lane >> 4) << 3) + (lane & 7);
                LDMX4(t4, base + brow * 80 + (kf * 16 + ((lane >> 3) & 1) * 8) * 2);
                uint32_t b0[2] = {t4[0], t4[1]}, b1[2] = {t4[2], t4[3]};
                MMA(oac[g * 2], a2, b0);
                MMA(oac[g * 2 + 1], a2, b1);
            }
        }
        __syncthreads();
    }

    float is0 = fIS[r0], is1 = fIS[r0 + 8];
    #pragma unroll
    for (int j = 0; j < 8; j++) {
        int col = wgn * 64 + j * 8 + (lane & 3) * 2;
        __half2 h0 = __floats2half2_rn(oac[j][0] * is0, oac[j][1] * is0);
        __half2 h1 = __floats2half2_rn(oac[j][2] * is1, oac[j][3] * is1);
        *(uint32_t*)(sm + (r0 * 264 + col) * 2)       = *(uint32_t*)&h0;
        *(uint32_t*)(sm + ((r0 + 8) * 264 + col) * 2) = *(uint32_t*)&h1;
    }
    __syncthreads();
    uint32_t* msg32 = (uint32_t*)msg;
    #pragma unroll
    for (int it = 0; it < 16; it++) {
        int idx = tid + it * 256, row = idx >> 7, col2 = idx & 127;
        uint32_t val = *(uint32_t*)(sm + (row * 264 + col2 * 2) * 2);
        msg32[((size_t)b * HWn + win_tok(wi, m0 + row)) * 128 + col2] = val;
    }
}

// ======================================================================
// GEMM-128 (unchanged): PROJ (z==2 writes V^T) and W1.
// ======================================================================
#define V_PROJ 0
#define V_WM   3
#define V_W1   4
#define V_W2   5

struct GP {
    const __half *A, *B;
    const __half *A2;
    const __half *Bx[3];
    __half *Ox[3];
    const float *resid, *lng, *lnb;
    float *outf;
    __half *outh;
    int K, Nout;
};

#define TILE128 16384
#define STG128  (2*TILE128)
#define G128_SMEM (3*STG128 + 1024)

template<int V>
__global__ void __launch_bounds__(256, 2)
mma_gemm128(GP p)
{
    extern __shared__ char smraw[];
    char* sm = (char*)((((uintptr_t)smraw) + 1023) & ~(uintptr_t)1023);
    uint32_t sb = smem_u32(sm);

    const int tid = threadIdx.x, wid = tid >> 5, lane = tid & 31;
    const int wm = (wid >> 1) * 32;
    const int wn = (wid & 1) * 64;

    const int n0 = blockIdx.x * 128;
    const int m0 = blockIdx.y * 128;
    const int KTOT = p.K, NCH = KTOT >> 6;

    const __half* Aptr = p.A;
    const __half* Bptr = p.B;
    __half* outh = p.outh;
    if constexpr (V == V_PROJ) {
        Aptr = blockIdx.z ? p.A2 : p.A;
        Bptr = p.Bx[blockIdx.z];
        outh = p.Ox[blockIdx.z];
    }

    float acc[2][8][4];
    #pragma unroll
    for (int i = 0; i < 2; i++)
        #pragma unroll
        for (int j = 0; j < 8; j++)
            #pragma unroll
            for (int e = 0; e < 4; e++) acc[i][j][e] = 0.f;

    auto fill = [&](int c) {
        uint32_t bb = sb + (c % 3) * STG128;
        int k0 = c << 6;
        #pragma unroll
        for (int it = 0; it < 4; it++) {
            int idx = tid + it * 256;
            int r = idx >> 3, qq = idx & 7;
            uint32_t o = SWZ((uint32_t)(r * 128 + qq * 16));
            const __half *pa;
            if constexpr (V == V_W1) {
                size_t row = (size_t)(m0 + r);
                pa = (k0 < 256) ? p.A + row * 256 + k0 + qq * 8
                                : p.A2 + row * 256 + (k0 - 256) + qq * 8;
            } else {
                pa = Aptr + (size_t)(m0 + r) * (size_t)KTOT + k0 + qq * 8;
            }
            CP16(bb + o, pa);
        }
        #pragma unroll
        for (int it = 0; it < 4; it++) {
            int idx = tid + it * 256;
            int r = idx >> 3, qq = idx & 7;
            uint32_t o = SWZ((uint32_t)(r * 128 + qq * 16));
            CP16(bb + TILE128 + o, Bptr + (size_t)(n0 + r) * (size_t)KTOT + k0 + qq * 8);
        }
        CP_COMMIT();
    };

    fill(0);
    if (NCH > 1) fill(1);
    for (int c = 0; c < NCH; c++) {
        if (c + 1 < NCH) CP_WAIT1(); else CP_WAIT0();
        __syncthreads();
        if (c + 2 < NCH) fill(c + 2);
        uint32_t bb = sb + (c % 3) * STG128;
        const uint32_t tA = bb, tB = bb + TILE128;
        #pragma unroll
        for (int kk = 0; kk < 4; kk++) {
            uint32_t afr[2][4];
            int arow = wm + (lane & 15);
            int acol = kk * 16 + (lane >> 4) * 8;
            #pragma unroll
            for (int mf = 0; mf < 2; mf++)
                LDMX4(afr[mf], tA + SWZ((uint32_t)((arow + mf * 16) * 128 + acol * 2)));
            int brow0 = wn + ((lane >> 4) << 3) + (lane & 7);
            int bcol = kk * 16 + ((lane >> 3) & 1) * 8;
            #pragma unroll
            for (int np = 0; np < 4; np++) {
                uint32_t t4[4];
                LDMX4(t4, tB + SWZ((uint32_t)((brow0 + np * 16) * 128 + bcol * 2)));
                uint32_t b0[2] = {t4[0], t4[1]}, b1[2] = {t4[2], t4[3]};
                #pragma unroll
                for (int mf = 0; mf < 2; mf++) {
                    MMA(acc[mf][np * 2],     afr[mf], b0);
                    MMA(acc[mf][np * 2 + 1], afr[mf], b1);
                }
            }
        }
        __syncthreads();
    }

    float* stg = (float*)sm;
    #pragma unroll
    for (int mf = 0; mf < 2; mf++)
        #pragma unroll
        for (int nf = 0; nf < 8; nf++) {
            int r0 = wm + mf * 16 + (lane >> 2);
            int c0 = wn + nf * 8 + (lane & 3) * 2;
            stg[r0 * 130 + c0]     = acc[mf][nf][0];
            stg[r0 * 130 + c0 + 1] = acc[mf][nf][1];
            stg[(r0 + 8) * 130 + c0]     = acc[mf][nf][2];
            stg[(r0 + 8) * 130 + c0 + 1] = acc[mf][nf][3];
        }
    __syncthreads();

    if constexpr (V == V_PROJ) {
        if (blockIdx.z == 2) {
            int bb2 = m0 >> 12, t0 = m0 & (HWn - 1);
            #pragma unroll
            for (int it = 0; it < 32; it++) {
                int e = tid + it * 256;
                int col = e >> 6, rp = e & 63;
                float v0 = stg[(2 * rp) * 130 + col];
                float v1 = stg[(2 * rp + 1) * 130 + col];
                __half2 h = __floats2half2_rn(v0, v1);
                *(__half2*)(outh + ((size_t)(bb2 * Dn + n0 + col)) * HWn + t0 + 2 * rp) = h;
            }
            return;
        }
    }
    #pragma unroll
    for (int it = 0; it < 16; it++) {
        int e = tid + it * 256;
        int row = e >> 5;
        int c4 = (e & 31) << 2;
        float4 v = make_float4(stg[row*130+c4], stg[row*130+c4+1],
                               stg[row*130+c4+2], stg[row*130+c4+3]);
        if constexpr (V == V_W1) {
            v.x = 0.5f * v.x * (1.f + erff(v.x * 0.70710678118654752f));
            v.y = 0.5f * v.y * (1.f + erff(v.y * 0.70710678118654752f));
            v.z = 0.5f * v.z * (1.f + erff(v.z * 0.70710678118654752f));
            v.w = 0.5f * v.w * (1.f + erff(v.w * 0.70710678118654752f));
        }
        size_t gi = (size_t)(m0 + row) * (size_t)p.Nout + n0 + c4;
        __half2* ph = (__half2*)(outh + gi);
        ph[0] = __floats2half2_rn(v.x, v.y);
        ph[1] = __floats2half2_rn(v.z, v.w);
    }
}

// ---------------- GEMM-256: CTA 128x256, 512 thr, 3-stage ------------------
// Register-level LN stats + conflict-free float4 drain (stride 260 = 16B-aligned).
#define ASIZE 16384
#define BSIZE 32768
#define STAGE (ASIZE+BSIZE)
#define SSTR  260                 // staging row stride (floats), 16B-aligned rows
#define OFF_GB   133120           // 128*260*4; gamma/beta: 512 floats
#define OFF_RED  135168           // s1[4][128], s2[4][128]: 4KB
#define OFF_MUSD 139264           // per-row (mu, rstd): 128 float2 = 1KB
#define GEMM_SMEM (3*STAGE + 1024)   // 148480 >= 140288 needed

template<int V>
__global__ void __launch_bounds__(512)
mma_gemm(GP p)
{
    extern __shared__ char smraw[];
    char* sm = (char*)((((uintptr_t)smraw) + 1023) & ~(uintptr_t)1023);
    uint32_t sb = smem_u32(sm);

    const int tid = threadIdx.x, wid = tid >> 5, lane = tid & 31;
    const int wm = (wid >> 2) * 32;
    const int wn = (wid & 3) * 64;

    const int n0 = blockIdx.x * 256;
    const int m0 = blockIdx.y * 128;
    const int KTOT = p.K, NCH = KTOT >> 6;

    float acc[2][8][4];
    #pragma unroll
    for (int i = 0; i < 2; i++)
        #pragma unroll
        for (int j = 0; j < 8; j++)
            #pragma unroll
            for (int e = 0; e < 4; e++) acc[i][j][e] = 0.f;

    auto fill = [&](int c) {
        uint32_t bb = sb + (c % 3) * STAGE;
        int k0 = c << 6;
        #pragma unroll
        for (int it = 0; it < 2; it++) {
            int idx = tid + it * 512;
            int r = idx >> 3, qq = idx & 7;
            uint32_t o = SWZ((uint32_t)(r * 128 + qq * 16));
            CP16(bb + o, p.A + (size_t)(m0 + r) * (size_t)KTOT + k0 + qq * 8);
        }
        #pragma unroll
        for (int it = 0; it < 4; it++) {
            int idx = tid + it * 512;
            int r = idx >> 3, qq = idx & 7;
            uint32_t o = SWZ((uint32_t)(r * 128 + qq * 16));
            CP16(bb + ASIZE + o, p.B + (size_t)(n0 + r) * (size_t)KTOT + k0 + qq * 8);
        }
        CP_COMMIT();
    };

    fill(0);
    if (NCH > 1) fill(1);
    for (int c = 0; c < NCH; c++) {
        if (c + 1 < NCH) CP_WAIT1(); else CP_WAIT0();
        __syncthreads();
        if (c + 2 < NCH) fill(c + 2);
        uint32_t bb = sb + (c % 3) * STAGE;
        const uint32_t tA = bb, tB = bb + ASIZE;
        #pragma unroll
        for (int kk = 0; kk < 4; kk++) {
            uint32_t afr[2][4];
            int arow = wm + (lane & 15);
            int acol = kk * 16 + (lane >> 4) * 8;
            #pragma unroll
            for (int mf = 0; mf < 2; mf++)
                LDMX4(afr[mf], tA + SWZ((uint32_t)((arow + mf * 16) * 128 + acol * 2)));
            int brow0 = wn + ((lane >> 4) << 3) + (lane & 7);
            int bcol = kk * 16 + ((lane >> 3) & 1) * 8;
            #pragma unroll
            for (int np = 0; np < 4; np++) {
                uint32_t t4[4];
                LDMX4(t4, tB + SWZ((uint32_t)((brow0 + np * 16) * 128 + bcol * 2)));
                uint32_t b0[2] = {t4[0], t4[1]}, b1[2] = {t4[2], t4[3]};
                #pragma unroll
                for (int mf = 0; mf < 2; mf++) {
                    MMA(acc[mf][np * 2],     afr[mf], b0);
                    MMA(acc[mf][np * 2 + 1], afr[mf], b1);
                }
            }
        }
        __syncthreads();
    }

    // ---- epilogue: register-level LN stats + conflict-free drain ----
    float* stg  = (float*)sm;                    // [128][SSTR]
    float* gb   = (float*)(sm + OFF_GB);         // gamma[256], beta[256]
    float* red1 = (float*)(sm + OFF_RED);        // [4][128]
    float* red2 = red1 + 512;                    // [4][128]
    float2* musd = (float2*)(sm + OFF_MUSD);     // [128]

    gb[tid & 511] = (tid < 256) ? p.lng[tid] : p.lnb[tid - 256];

    // per-thread partial sums over the 4 rows this thread touches
    float s1r[4] = {}, s2r[4] = {};
    #pragma unroll
    for (int mf = 0; mf < 2; mf++)
        #pragma unroll
        for (int nf = 0; nf < 8; nf++) {
            float a0 = acc[mf][nf][0], a1 = acc[mf][nf][1];
            float a2 = acc[mf][nf][2], a3 = acc[mf][nf][3];
            s1r[mf*2]   += a0 + a1;   s2r[mf*2]   += a0*a0 + a1*a1;
            s1r[mf*2+1] += a2 + a3;   s2r[mf*2+1] += a2*a2 + a3*a3;
        }
    #pragma unroll
    for (int off = 1; off <= 2; off <<= 1)
        #pragma unroll
        for (int i = 0; i < 4; i++) {
            s1r[i] += __shfl_xor_sync(0xffffffff, s1r[i], off);
            s2r[i] += __shfl_xor_sync(0xffffffff, s2r[i], off);
        }
    if ((lane & 3) == 0) {
        int wgn = wid & 3;
        #pragma unroll
        for (int i = 0; i < 4; i++) {
            // i = mf*2 + half: rows are wm + mf*16 + half*8 + (lane>>2)
            int row = wm + (i >> 1) * 16 + (i & 1) * 8 + (lane >> 2);
            red1[wgn * 128 + row] = s1r[i];
            red2[wgn * 128 + row] = s2r[i];
        }
    }

    // stage acc tile
    #pragma unroll
    for (int mf = 0; mf < 2; mf++)
        #pragma unroll
        for (int nf = 0; nf < 8; nf++) {
            int r0 = wm + mf * 16 + (lane >> 2);
            int c0 = wn + nf * 8 + (lane & 3) * 2;
            stg[r0 * SSTR + c0]     = acc[mf][nf][0];
            stg[r0 * SSTR + c0 + 1] = acc[mf][nf][1];
            stg[(r0 + 8) * SSTR + c0]     = acc[mf][nf][2];
            stg[(r0 + 8) * SSTR + c0 + 1] = acc[mf][nf][3];
        }
    __syncthreads();

    if (tid < 128) {
        float s1 = red1[tid] + red1[128 + tid] + red1[256 + tid] + red1[384 + tid];
        float s2 = red2[tid] + red2[128 + tid] + red2[256 + tid] + red2[384 + tid];
        float mu = s1 * (1.f / 256.f);
        float rstd = rsqrtf(s2 * (1.f / 256.f) - mu * mu + 1e-5f);
        musd[tid] = make_float2(mu, rstd);
    }
    __syncthreads();

    // conflict-free row-major drain: 512 thr x 16 iters x float4
    #pragma unroll
    for (int it = 0; it < 16; it++) {
        int e = tid + it * 512;
        int row = e >> 6;
        int c4 = (e & 63) << 2;
        float4 v = *(float4*)&stg[row * SSTR + c4];
        float2 ms = musd[row];
        float4 g4 = *(float4*)&gb[c4];
        float4 b4 = *(float4*)&gb[256 + c4];
        v.x = (v.x - ms.x) * ms.y * g4.x + b4.x;
        v.y = (v.y - ms.x) * ms.y * g4.y + b4.y;
        v.z = (v.z - ms.x) * ms.y * g4.z + b4.z;
        v.w = (v.w - ms.x) * ms.y * g4.w + b4.w;
        size_t gi = (size_t)(m0 + row) * 256 + c4;
        if constexpr (V == V_WM) {
            __half2* ph = (__half2*)(p.outh + gi);
            ph[0] = __floats2half2_rn(v.x, v.y);
            ph[1] = __floats2half2_rn(v.z, v.w);
        } else {
            float4 rs = *(const float4*)&p.resid[gi];
            v.x += rs.x; v.y += rs.y; v.z += rs.z; v.w += rs.w;
            *(float4*)&p.outf[gi] = v;
        }
    }
}

// ---------------- host -------------------------------------------------------
extern "C" void kernel_launch(void* const* d_in, const int* in_sizes, int n_in,
                              void* d_out, int out_size)
{
    const float* source = (const float*)d_in[0];
    const float* target = (const float*)d_in[1];
    const float* mask   = (const float*)d_in[2];
    const float* Wq     = (const float*)d_in[3];
    const float* Wk     = (const float*)d_in[4];
    const float* Wv     = (const float*)d_in[5];
    const float* Wm     = (const float*)d_in[6];
    const float* ln1g   = (const float*)d_in[7];
    const float* ln1b   = (const float*)d_in[8];
    const float* W1     = (const float*)d_in[9];
    const float* W2     = (const float*)d_in[10];
    const float* ln2g   = (const float*)d_in[11];
    const float* ln2b   = (const float*)d_in[12];
    float* out = (float*)d_out;

    #define SYM(p, s) void* p; cudaGetSymbolAddress(&p, s)
    SYM(srcp, g_src); SYM(tgtp, g_tgt);
    SYM(wqp, g_wq); SYM(wkp, g_wk); SYM(wvp, g_wv); SYM(wmp, g_wm);
    SYM(w1p, g_w1); SYM(w2p, g_w2);
    SYM(qp, g_q); SYM(kp, g_k); SYM(vtp, g_vt);
    SYM(msgp, g_msg); SYM(msgnp, g_msgn); SYM(hidp, g_hid);
    #undef SYM

    cudaFuncSetAttribute(mma_gemm128<V_PROJ>, cudaFuncAttributeMaxDynamicSharedMemorySize, G128_SMEM);
    cudaFuncSetAttribute(mma_gemm128<V_W1>,   cudaFuncAttributeMaxDynamicSharedMemorySize, G128_SMEM);
    cudaFuncSetAttribute(mma_gemm<V_WM>,      cudaFuncAttributeMaxDynamicSharedMemorySize, GEMM_SMEM);
    cudaFuncSetAttribute(mma_gemm<V_W2>,      cudaFuncAttributeMaxDynamicSharedMemorySize, GEMM_SMEM);
    cudaFuncSetAttribute(flash_kernel,        cudaFuncAttributeMaxDynamicSharedMemorySize, FLASH_SMEM);

    // merged fp32 -> fp16 conversion (single launch)
    {
        CvtP cp;
        const float* ins[8]  = {source, target, Wq, Wk, Wv, Wm, W1, W2};
        void* outs[8]        = {srcp, tgtp, wqp, wkp, wvp, wmp, w1p, w2p};
        int n2s[8] = {Mtot*Dn/2, Mtot*Dn/2, Dn*Dn/2, Dn*Dn/2, Dn*Dn/2, Dn*Dn/2,
                      DHn*2*Dn/2, Dn*DHn/2};
        int acc = 0;
        for (int j = 0; j < 8; j++) {
            cp.in[j] = (const float2*)ins[j];
            cp.out[j] = (__half2*)outs[j];
            acc += n2s[j];
            cp.end[j] = acc;
        }
        cvt_all_kernel<<<(acc + 255) / 256, 256>>>(cp);
    }

    GP p;

    // fused Q/K/V projections: z==2 writes V transposed into g_vt
    p = GP{};
    p.A  = (const __half*)srcp;
    p.A2 = (const __half*)tgtp;
    p.Bx[0] = (const __half*)wqp; p.Bx[1] = (const __half*)wkp; p.Bx[2] = (const __half*)wvp;
    p.Ox[0] = (__half*)qp;        p.Ox[1] = (__half*)kp;        p.Ox[2] = (__half*)vtp;
    p.K = Dn; p.Nout = Dn;
    mma_gemm128<V_PROJ><<<dim3(2, Mtot/128, 3), 256, G128_SMEM>>>(p);

    // fused attention
    flash_kernel<<<dim3(LWn/32, NWn), 256, FLASH_SMEM>>>(
        (const __half*)qp, (const __half*)kp, (const __half*)vtp, mask, (__half*)msgp);

    // msg @ Wm^T with fused LN1 -> fp16 msgn
    p = GP{}; p.A=(const __half*)msgp; p.B=(const __half*)wmp;
    p.lng=ln1g; p.lnb=ln1b; p.outh=(__half*)msgnp; p.K=Dn; p.Nout=Dn;
    mma_gemm<V_WM><<<dim3(1, Mtot/128), 512, GEMM_SMEM>>>(p);

    // hid = gelu([source, msg] @ W1^T)
    p = GP{}; p.A=(const __half*)srcp; p.A2=(const __half*)msgnp;
    p.B=(const __half*)w1p;
    p.outh=(__half*)hidp; p.K=2*Dn; p.Nout=DHn;
    mma_gemm128<V_W1><<<dim3(DHn/128, Mtot/128), 256, G128_SMEM>>>(p);

    // out = source + LN2(hid @ W2^T)
    p = GP{}; p.A=(const __half*)hidp; p.B=(const __half*)w2p;
    p.lng=ln2g; p.lnb=ln2b; p.resid=source; p.outf=out; p.K=DHn; p.Nout=Dn;
    mma_gemm<V_W2><<<dim3(1, Mtot/128), 512, GEMM_SMEM>>>(p);
}

// round 16
// speedup vs baseline: 1.4970x; 1.4970x over previous
#include <cuda_runtime.h>
#include <cuda_fp16.h>
#include <math.h>
#include <stdint.h>

#define Bn 8
#define HWn 4096
#define Dn 256
#define LWn 1024
#define NWn 32
#define DHn 2048
#define Mtot (Bn*HWn)

// ---------------- scratch (device globals; allocation is forbidden) --------
#define AL16 __align__(16)
__device__ AL16 __half g_src[Mtot*Dn];
__device__ AL16 __half g_tgt[Mtot*Dn];
__device__ AL16 __half g_wq[Dn*Dn], g_wk[Dn*Dn], g_wv[Dn*Dn], g_wm[Dn*Dn];
__device__ AL16 __half g_w1[DHn*2*Dn];
__device__ AL16 __half g_w2[Dn*DHn];
__device__ AL16 __half g_q[Mtot*Dn], g_k[Mtot*Dn], g_vt[Mtot*Dn];
__device__ AL16 __half g_msg[Mtot*Dn];
__device__ AL16 __half g_msgn[Mtot*Dn];
__device__ AL16 __half g_hid[(size_t)Mtot*DHn];

// ---------------- portable PTX helpers (sm_80+ class only) -----------------
__device__ __forceinline__ uint32_t smem_u32(const void* p) {
    uint32_t a;
    asm("{ .reg .u64 t; cvta.to.shared.u64 t, %1; cvt.u32.u64 %0, t; }" : "=r"(a) : "l"(p));
    return a;
}
#define SWZ(o) ((o) ^ (((o) >> 3) & 0x70))

#define CP16(dst, src) asm volatile("cp.async.cg.shared.global [%0],[%1],16;" \
    :: "r"(dst), "l"(__cvta_generic_to_global(src)) : "memory")
#define CP_COMMIT() asm volatile("cp.async.commit_group;" ::: "memory")
#define CP_WAIT1()  asm volatile("cp.async.wait_group 1;" ::: "memory")
#define CP_WAIT0()  asm volatile("cp.async.wait_group 0;" ::: "memory")

#define LDMX4(r, a) asm volatile("ldmatrix.sync.aligned.m8n8.x4.shared.b16 {%0,%1,%2,%3},[%4];" \
    : "=r"((r)[0]), "=r"((r)[1]), "=r"((r)[2]), "=r"((r)[3]) : "r"(a))
#define LDMX2(r, a) asm volatile("ldmatrix.sync.aligned.m8n8.x2.shared.b16 {%0,%1},[%2];" \
    : "=r"((r)[0]), "=r"((r)[1]) : "r"(a))

#define MMA(d, a, b) asm volatile( \
    "mma.sync.aligned.m16n8k16.row.col.f32.f16.f16.f32 " \
    "{%0,%1,%2,%3},{%4,%5,%6,%7},{%8,%9},{%0,%1,%2,%3};" \
    : "+f"((d)[0]), "+f"((d)[1]), "+f"((d)[2]), "+f"((d)[3]) \
    : "r"((a)[0]), "r"((a)[1]), "r"((a)[2]), "r"((a)[3]), "r"((b)[0]), "r"((b)[1]))

// window-token permutation: roll(-16,-16) + 2x2 window split
__device__ __forceinline__ int win_tok(int wi, int l) {
    int i = l >> 5, j = l & 31;
    int y = (((wi >> 1) << 5) + i + 16) & 63;
    int x = (((wi &  1) << 5) + j + 16) & 63;
    return (y << 6) | x;
}

// ---------------- merged fp32 -> fp16 conversion (one launch) ---------------
struct CvtP {
    const float2* in[8];
    __half2* out[8];
    int end[8];
};
__global__ void cvt_all_kernel(CvtP p)
{
    int i = blockIdx.x * 256 + threadIdx.x;
    if (i >= p.end[7]) return;
    int s = 0;
    #pragma unroll
    for (int j = 0; j < 7; j++) s += (i >= p.end[j]);
    int base = (s == 0) ? 0 : p.end[s - 1];
    p.out[s][i - base] = __float22half2_rn(p.in[s][i - base]);
}

// ======================================================================
// Fused window attention v5 (R11/R12 — known good, protected)
// ======================================================================
#define PSTR    1032
#define OFF_P   0
#define OFF_KV  66048
#define KB32    16896
#define VB32    20480
#define OFF_SS  107008
#define OFF_FIS 107520
#define FLASH_SMEM 107648

__global__ void __launch_bounds__(256, 2)
flash_kernel(const __half* __restrict__ q, const __half* __restrict__ k,
             const __half* __restrict__ vt, const float* __restrict__ mask,
             __half* __restrict__ msg)
{
    extern __shared__ char sm[];
    uint32_t sb = smem_u32(sm);
    const int tid = threadIdx.x, wid = tid >> 5, lane = tid & 31;
    const int wgm = wid >> 2, wgn = wid & 3;
    const int m0 = blockIdx.x * 32;
    const int bw = blockIdx.y, b = bw >> 2, wi = bw & 3;
    const float* maskw = mask + (size_t)wi * LWn * LWn;

    #pragma unroll
    for (int it = 0; it < 4; it++) {
        int idx = tid + it * 256, row = idx >> 5, seg = idx & 31;
        const __half* src = q + ((size_t)b * HWn + win_tok(wi, m0 + row)) * Dn + seg * 8;
        CP16(sb + OFF_KV + row * 528 + seg * 16, src);
    }
    CP_COMMIT(); CP_WAIT0(); __syncthreads();
    uint32_t af[16][4];
    {
        int qrow = wgm * 16 + (lane & 15);
        #pragma unroll
        for (int kf = 0; kf < 16; kf++)
            LDMX4(af[kf], sb + OFF_KV + qrow * 528 + (kf * 16 + (lane >> 4) * 8) * 2);
    }
    __syncthreads();

    const int r0 = wgm * 16 + (lane >> 2);
    float srun0 = 0.f, srun1 = 0.f;

    auto fillK = [&](int ch) {
        uint32_t base = sb + OFF_KV + (ch & 1) * KB32;
        int kc = ch * 32;
        #pragma unroll
        for (int it = 0; it < 4; it++) {
            int idx = tid + it * 256, row = idx >> 5, seg = idx & 31;
            const __half* src = k + ((size_t)b * HWn + win_tok(wi, kc + row)) * Dn + seg * 8;
            CP16(base + row * 528 + seg * 16, src);
        }
        CP_COMMIT();
    };
    fillK(0);
    {
        const int key = wgn * 8 + (lane & 7);
        const int koff = ((lane >> 3) & 1) * 8;
        for (int ch = 0; ch < 32; ch++) {
            if (ch + 1 < 32) { fillK(ch + 1); CP_WAIT1(); } else CP_WAIT0();
            __syncthreads();
            int kc = ch * 32;
            int col = kc + wgn * 8 + (lane & 3) * 2;
            float2 mk0 = *(const float2*)&maskw[(size_t)(m0 + r0) * LWn + col];
            float2 mk1 = *(const float2*)&maskw[(size_t)(m0 + r0 + 8) * LWn + col];
            uint32_t base = sb + OFF_KV + (ch & 1) * KB32;
            float sac[4] = {};
            #pragma unroll
            for (int kf = 0; kf < 16; kf++) {
                uint32_t t2[2];
                LDMX2(t2, base + key * 528 + (kf * 16 + koff) * 2);
                MMA(sac, af[kf], t2);
            }
            float p0 = exp2f(fmaf(sac[0] * 0.0625f + mk0.x, 1.4426950408889634f, -2.8853900817779268f));
            float p1 = exp2f(fmaf(sac[1] * 0.0625f + mk0.y, 1.4426950408889634f, -2.8853900817779268f));
            float p2 = exp2f(fmaf(sac[2] * 0.0625f + mk1.x, 1.4426950408889634f, -2.8853900817779268f));
            float p3 = exp2f(fmaf(sac[3] * 0.0625f + mk1.y, 1.4426950408889634f, -2.8853900817779268f));
            srun0 += p0 + p1;
            srun1 += p2 + p3;
            __half2 h0 = __floats2half2_rn(p0, p1);
            __half2 h1 = __floats2half2_rn(p2, p3);
            *(uint32_t*)(sm + OFF_P + (r0 * PSTR + col) * 2)       = *(uint32_t*)&h0;
            *(uint32_t*)(sm + OFF_P + ((r0 + 8) * PSTR + col) * 2) = *(uint32_t*)&h1;
            __syncthreads();
        }
    }
    #pragma unroll
    for (int off = 1; off <= 2; off <<= 1) {
        srun0 += __shfl_xor_sync(0xffffffff, srun0, off);
        srun1 += __shfl_xor_sync(0xffffffff, srun1, off);
    }
    float* smS = (float*)(sm + OFF_SS);
    if ((lane & 3) == 0) {
        smS[wgn * 32 + r0] = srun0;
        smS[wgn * 32 + r0 + 8] = srun1;
    }
    __syncthreads();
    float* fIS = (float*)(sm + OFF_FIS);
    if (tid < 32) {
        float ss = smS[tid] + smS[32 + tid] + smS[64 + tid] + smS[96 + tid];
        fIS[tid] = 1.f / ss;
    }
    __syncthreads();

    float oac[8][4] = {};
    auto fillV = [&](int ch) {
        uint32_t base = sb + OFF_KV + (ch & 1) * VB32;
        int kc = ch * 32;
        #pragma unroll
        for (int it = 0; it < 4; it++) {
            int idx = tid + it * 256, row = idx >> 2, seg = idx & 3;
            const __half* src = vt + ((size_t)b * Dn + row) * (size_t)HWn + win_tok(wi, kc + seg * 8);
            CP16(base + row * 80 + seg * 16, src);
        }
        CP_COMMIT();
    };
    fillV(0);
    const int prow = wgm * 16 + (lane & 15);
    const uint32_t pbase = sb + OFF_P + prow * (PSTR * 2);
    for (int ch = 0; ch < 32; ch++) {
        if (ch + 1 < 32) { fillV(ch + 1); CP_WAIT1(); } else CP_WAIT0();
        __syncthreads();
        uint32_t base = sb + OFF_KV + (ch & 1) * VB32;
        int kc = ch * 32;
        #pragma unroll
        for (int kf = 0; kf < 2; kf++) {
            uint32_t a2[4];
            LDMX4(a2, pbase + (kc + kf * 16 + (lane >> 4) * 8) * 2);
            #pragma unroll
            for (int g = 0; g < 4; g++) {
                uint32_t t4[4];
                int brow = wgn * 64 + g * 16 + ((lane >> 4) << 3) + (lane & 7);
                LDMX4(t4, base + brow * 80 + (kf * 16 + ((lane >> 3) & 1) * 8) * 2);
                uint32_t b0[2] = {t4[0], t4[1]}, b1[2] = {t4[2], t4[3]};
                MMA(oac[g * 2], a2, b0);
                MMA(oac[g * 2 + 1], a2, b1);
            }
        }
        __syncthreads();
    }

    float is0 = fIS[r0], is1 = fIS[r0 + 8];
    #pragma unroll
    for (int j = 0; j < 8; j++) {
        int col = wgn * 64 + j * 8 + (lane & 3) * 2;
        __half2 h0 = __floats2half2_rn(oac[j][0] * is0, oac[j][1] * is0);
        __half2 h1 = __floats2half2_rn(oac[j][2] * is1, oac[j][3] * is1);
        *(uint32_t*)(sm + (r0 * 264 + col) * 2)       = *(uint32_t*)&h0;
        *(uint32_t*)(sm + ((r0 + 8) * 264 + col) * 2) = *(uint32_t*)&h1;
    }
    __syncthreads();
    uint32_t* msg32 = (uint32_t*)msg;
    #pragma unroll
    for (int it = 0; it < 16; it++) {
        int idx = tid + it * 256, row = idx >> 7, col2 = idx & 127;
        uint32_t val = *(uint32_t*)(sm + (row * 264 + col2 * 2) * 2);
        msg32[((size_t)b * HWn + win_tok(wi, m0 + row)) * 128 + col2] = val;
    }
}

// ======================================================================
// GEMM-128 (unchanged): PROJ (z==2 writes V^T) and W1.
// ======================================================================
#define V_PROJ 0
#define V_WM   3
#define V_W1   4
#define V_W2   5

struct GP {
    const __half *A, *B;
    const __half *A2;
    const __half *Bx[3];
    __half *Ox[3];
    const float *resid, *lng, *lnb;
    float *outf;
    __half *outh;
    int K, Nout;
};

#define TILE128 16384
#define STG128  (2*TILE128)
#define G128_SMEM (3*STG128 + 1024)

template<int V>
__global__ void __launch_bounds__(256, 2)
mma_gemm128(GP p)
{
    extern __shared__ char smraw[];
    char* sm = (char*)((((uintptr_t)smraw) + 1023) & ~(uintptr_t)1023);
    uint32_t sb = smem_u32(sm);

    const int tid = threadIdx.x, wid = tid >> 5, lane = tid & 31;
    const int wm = (wid >> 1) * 32;
    const int wn = (wid & 1) * 64;

    const int n0 = blockIdx.x * 128;
    const int m0 = blockIdx.y * 128;
    const int KTOT = p.K, NCH = KTOT >> 6;

    const __half* Aptr = p.A;
    const __half* Bptr = p.B;
    __half* outh = p.outh;
    if constexpr (V == V_PROJ) {
        Aptr = blockIdx.z ? p.A2 : p.A;
        Bptr = p.Bx[blockIdx.z];
        outh = p.Ox[blockIdx.z];
    }

    float acc[2][8][4];
    #pragma unroll
    for (int i = 0; i < 2; i++)
        #pragma unroll
        for (int j = 0; j < 8; j++)
            #pragma unroll
            for (int e = 0; e < 4; e++) acc[i][j][e] = 0.f;

    auto fill = [&](int c) {
        uint32_t bb = sb + (c % 3) * STG128;
        int k0 = c << 6;
        #pragma unroll
        for (int it = 0; it < 4; it++) {
            int idx = tid + it * 256;
            int r = idx >> 3, qq = idx & 7;
            uint32_t o = SWZ((uint32_t)(r * 128 + qq * 16));
            const __half *pa;
            if constexpr (V == V_W1) {
                size_t row = (size_t)(m0 + r);
                pa = (k0 < 256) ? p.A + row * 256 + k0 + qq * 8
                                : p.A2 + row * 256 + (k0 - 256) + qq * 8;
            } else {
                pa = Aptr + (size_t)(m0 + r) * (size_t)KTOT + k0 + qq * 8;
            }
            CP16(bb + o, pa);
        }
        #pragma unroll
        for (int it = 0; it < 4; it++) {
            int idx = tid + it * 256;
            int r = idx >> 3, qq = idx & 7;
            uint32_t o = SWZ((uint32_t)(r * 128 + qq * 16));
            CP16(bb + TILE128 + o, Bptr + (size_t)(n0 + r) * (size_t)KTOT + k0 + qq * 8);
        }
        CP_COMMIT();
    };

    fill(0);
    if (NCH > 1) fill(1);
    for (int c = 0; c < NCH; c++) {
        if (c + 1 < NCH) CP_WAIT1(); else CP_WAIT0();
        __syncthreads();
        if (c + 2 < NCH) fill(c + 2);
        uint32_t bb = sb + (c % 3) * STG128;
        const uint32_t tA = bb, tB = bb + TILE128;
        #pragma unroll
        for (int kk = 0; kk < 4; kk++) {
            uint32_t afr[2][4];
            int arow = wm + (lane & 15);
            int acol = kk * 16 + (lane >> 4) * 8;
            #pragma unroll
            for (int mf = 0; mf < 2; mf++)
                LDMX4(afr[mf], tA + SWZ((uint32_t)((arow + mf * 16) * 128 + acol * 2)));
            int brow0 = wn + ((lane >> 4) << 3) + (lane & 7);
            int bcol = kk * 16 + ((lane >> 3) & 1) * 8;
            #pragma unroll
            for (int np = 0; np < 4; np++) {
                uint32_t t4[4];
                LDMX4(t4, tB + SWZ((uint32_t)((brow0 + np * 16) * 128 + bcol * 2)));
                uint32_t b0[2] = {t4[0], t4[1]}, b1[2] = {t4[2], t4[3]};
                #pragma unroll
                for (int mf = 0; mf < 2; mf++) {
                    MMA(acc[mf][np * 2],     afr[mf], b0);
                    MMA(acc[mf][np * 2 + 1], afr[mf], b1);
                }
            }
        }
        __syncthreads();
    }

    float* stg = (float*)sm;
    #pragma unroll
    for (int mf = 0; mf < 2; mf++)
        #pragma unroll
        for (int nf = 0; nf < 8; nf++) {
            int r0 = wm + mf * 16 + (lane >> 2);
            int c0 = wn + nf * 8 + (lane & 3) * 2;
            stg[r0 * 130 + c0]     = acc[mf][nf][0];
            stg[r0 * 130 + c0 + 1] = acc[mf][nf][1];
            stg[(r0 + 8) * 130 + c0]     = acc[mf][nf][2];
            stg[(r0 + 8) * 130 + c0 + 1] = acc[mf][nf][3];
        }
    __syncthreads();

    if constexpr (V == V_PROJ) {
        if (blockIdx.z == 2) {
            int bb2 = m0 >> 12, t0 = m0 & (HWn - 1);
            #pragma unroll
            for (int it = 0; it < 32; it++) {
                int e = tid + it * 256;
                int col = e >> 6, rp = e & 63;
                float v0 = stg[(2 * rp) * 130 + col];
                float v1 = stg[(2 * rp + 1) * 130 + col];
                __half2 h = __floats2half2_rn(v0, v1);
                *(__half2*)(outh + ((size_t)(bb2 * Dn + n0 + col)) * HWn + t0 + 2 * rp) = h;
            }
            return;
        }
    }
    #pragma unroll
    for (int it = 0; it < 16; it++) {
        int e = tid + it * 256;
        int row = e >> 5;
        int c4 = (e & 31) << 2;
        float4 v = make_float4(stg[row*130+c4], stg[row*130+c4+1],
                               stg[row*130+c4+2], stg[row*130+c4+3]);
        if constexpr (V == V_W1) {
            v.x = 0.5f * v.x * (1.f + erff(v.x * 0.70710678118654752f));
            v.y = 0.5f * v.y * (1.f + erff(v.y * 0.70710678118654752f));
            v.z = 0.5f * v.z * (1.f + erff(v.z * 0.70710678118654752f));
            v.w = 0.5f * v.w * (1.f + erff(v.w * 0.70710678118654752f));
        }
        size_t gi = (size_t)(m0 + row) * (size_t)p.Nout + n0 + c4;
        __half2* ph = (__half2*)(outh + gi);
        ph[0] = __floats2half2_rn(v.x, v.y);
        ph[1] = __floats2half2_rn(v.z, v.w);
    }
}

// ---------------- GEMM-256: CTA 128x256, 512 thr, 3-stage ------------------
// Register-level LN stats + conflict-free float4 drain (stride 260 = 16B-aligned).
#define ASIZE 16384
#define BSIZE 32768
#define STAGE (ASIZE+BSIZE)
#define SSTR  260                 // staging row stride (floats), 16B-aligned rows
#define OFF_GB   133120           // 128*260*4; gamma/beta: 512 floats
#define OFF_RED  135168           // s1[4][128], s2[4][128]: 4KB
#define OFF_MUSD 139264           // per-row (mu, rstd): 128 float2 = 1KB
#define GEMM_SMEM (3*STAGE + 1024)   // 148480 >= 140288 needed

template<int V>
__global__ void __launch_bounds__(512)
mma_gemm(GP p)
{
    extern __shared__ char smraw[];
    char* sm = (char*)((((uintptr_t)smraw) + 1023) & ~(uintptr_t)1023);
    uint32_t sb = smem_u32(sm);

    const int tid = threadIdx.x, wid = tid >> 5, lane = tid & 31;
    const int wm = (wid >> 2) * 32;
    const int wn = (wid & 3) * 64;

    const int n0 = blockIdx.x * 256;
    const int m0 = blockIdx.y * 128;
    const int KTOT = p.K, NCH = KTOT >> 6;

    float acc[2][8][4];
    #pragma unroll
    for (int i = 0; i < 2; i++)
        #pragma unroll
        for (int j = 0; j < 8; j++)
            #pragma unroll
            for (int e = 0; e < 4; e++) acc[i][j][e] = 0.f;

    auto fill = [&](int c) {
        uint32_t bb = sb + (c % 3) * STAGE;
        int k0 = c << 6;
        #pragma unroll
        for (int it = 0; it < 2; it++) {
            int idx = tid + it * 512;
            int r = idx >> 3, qq = idx & 7;
            uint32_t o = SWZ((uint32_t)(r * 128 + qq * 16));
            CP16(bb + o, p.A + (size_t)(m0 + r) * (size_t)KTOT + k0 + qq * 8);
        }
        #pragma unroll
        for (int it = 0; it < 4; it++) {
            int idx = tid + it * 512;
            int r = idx >> 3, qq = idx & 7;
            uint32_t o = SWZ((uint32_t)(r * 128 + qq * 16));
            CP16(bb + ASIZE + o, p.B + (size_t)(n0 + r) * (size_t)KTOT + k0 + qq * 8);
        }
        CP_COMMIT();
    };

    fill(0);
    if (NCH > 1) fill(1);
    for (int c = 0; c < NCH; c++) {
        if (c + 1 < NCH) CP_WAIT1(); else CP_WAIT0();
        __syncthreads();
        if (c + 2 < NCH) fill(c + 2);
        uint32_t bb = sb + (c % 3) * STAGE;
        const uint32_t tA = bb, tB = bb + ASIZE;
        #pragma unroll
        for (int kk = 0; kk < 4; kk++) {
            uint32_t afr[2][4];
            int arow = wm + (lane & 15);
            int acol = kk * 16 + (lane >> 4) * 8;
            #pragma unroll
            for (int mf = 0; mf < 2; mf++)
                LDMX4(afr[mf], tA + SWZ((uint32_t)((arow + mf * 16) * 128 + acol * 2)));
            int brow0 = wn + ((lane >> 4) << 3) + (lane & 7);
            int bcol = kk * 16 + ((lane >> 3) & 1) * 8;
            #pragma unroll
            for (int np = 0; np < 4; np++) {
                uint32_t t4[4];
                LDMX4(t4, tB + SWZ((uint32_t)((brow0 + np * 16) * 128 + bcol * 2)));
                uint32_t b0[2] = {t4[0], t4[1]}, b1[2] = {t4[2], t4[3]};
                #pragma unroll
                for (int mf = 0; mf < 2; mf++) {
                    MMA(acc[mf][np * 2],     afr[mf], b0);
                    MMA(acc[mf][np * 2 + 1], afr[mf], b1);
                }
            }
        }
        __syncthreads();
    }

    // ---- epilogue: register-level LN stats + conflict-free drain ----
    float* stg  = (float*)sm;                    // [128][SSTR]
    float* gb   = (float*)(sm + OFF_GB);         // gamma[256], beta[256]
    float* red1 = (float*)(sm + OFF_RED);        // [4][128]
    float* red2 = red1 + 512;                    // [4][128]
    float2* musd = (float2*)(sm + OFF_MUSD);     // [128]

    gb[tid & 511] = (tid < 256) ? p.lng[tid] : p.lnb[tid - 256];

    // per-thread partial sums over the 4 rows this thread touches
    float s1r[4] = {}, s2r[4] = {};
    #pragma unroll
    for (int mf = 0; mf < 2; mf++)
        #pragma unroll
        for (int nf = 0; nf < 8; nf++) {
            float a0 = acc[mf][nf][0], a1 = acc[mf][nf][1];
            float a2 = acc[mf][nf][2], a3 = acc[mf][nf][3];
            s1r[mf*2]   += a0 + a1;   s2r[mf*2]   += a0*a0 + a1*a1;
            s1r[mf*2+1] += a2 + a3;   s2r[mf*2+1] += a2*a2 + a3*a3;
        }
    #pragma unroll
    for (int off = 1; off <= 2; off <<= 1)
        #pragma unroll
        for (int i = 0; i < 4; i++) {
            s1r[i] += __shfl_xor_sync(0xffffffff, s1r[i], off);
            s2r[i] += __shfl_xor_sync(0xffffffff, s2r[i], off);
        }
    if ((lane & 3) == 0) {
        int wgn = wid & 3;
        #pragma unroll
        for (int i = 0; i < 4; i++) {
            // i = mf*2 + half: rows are wm + mf*16 + half*8 + (lane>>2)
            int row = wm + (i >> 1) * 16 + (i & 1) * 8 + (lane >> 2);
            red1[wgn * 128 + row] = s1r[i];
            red2[wgn * 128 + row] = s2r[i];
        }
    }

    // stage acc tile
    #pragma unroll
    for (int mf = 0; mf < 2; mf++)
        #pragma unroll
        for (int nf = 0; nf < 8; nf++) {
            int r0 = wm + mf * 16 + (lane >> 2);
            int c0 = wn + nf * 8 + (lane & 3) * 2;
            stg[r0 * SSTR + c0]     = acc[mf][nf][0];
            stg[r0 * SSTR + c0 + 1] = acc[mf][nf][1];
            stg[(r0 + 8) * SSTR + c0]     = acc[mf][nf][2];
            stg[(r0 + 8) * SSTR + c0 + 1] = acc[mf][nf][3];
        }
    __syncthreads();

    if (tid < 128) {
        float s1 = red1[tid] + red1[128 + tid] + red1[256 + tid] + red1[384 + tid];
        float s2 = red2[tid] + red2[128 + tid] + red2[256 + tid] + red2[384 + tid];
        float mu = s1 * (1.f / 256.f);
        float rstd = rsqrtf(s2 * (1.f / 256.f) - mu * mu + 1e-5f);
        musd[tid] = make_float2(mu, rstd);
    }
    __syncthreads();

    // conflict-free row-major drain: 512 thr x 16 iters x float4
    #pragma unroll
    for (int it = 0; it < 16; it++) {
        int e = tid + it * 512;
        int row = e >> 6;
        int c4 = (e & 63) << 2;
        float4 v = *(float4*)&stg[row * SSTR + c4];
        float2 ms = musd[row];
        float4 g4 = *(float4*)&gb[c4];
        float4 b4 = *(float4*)&gb[256 + c4];
        v.x = (v.x - ms.x) * ms.y * g4.x + b4.x;
        v.y = (v.y - ms.x) * ms.y * g4.y + b4.y;
        v.z = (v.z - ms.x) * ms.y * g4.z + b4.z;
        v.w = (v.w - ms.x) * ms.y * g4.w + b4.w;
        size_t gi = (size_t)(m0 + row) * 256 + c4;
        if constexpr (V == V_WM) {
            __half2* ph = (__half2*)(p.outh + gi);
            ph[0] = __floats2half2_rn(v.x, v.y);
            ph[1] = __floats2half2_rn(v.z, v.w);
        } else {
            float4 rs = *(const float4*)&p.resid[gi];
            v.x += rs.x; v.y += rs.y; v.z += rs.z; v.w += rs.w;
            *(float4*)&p.outf[gi] = v;
        }
    }
}

// ---------------- host -------------------------------------------------------
extern "C" void kernel_launch(void* const* d_in, const int* in_sizes, int n_in,
                              void* d_out, int out_size)
{
    const float* source = (const float*)d_in[0];
    const float* target = (const float*)d_in[1];
    const float* mask   = (const float*)d_in[2];
    const float* Wq     = (const float*)d_in[3];
    const float* Wk     = (const float*)d_in[4];
    const float* Wv     = (const float*)d_in[5];
    const float* Wm     = (const float*)d_in[6];
    const float* ln1g   = (const float*)d_in[7];
    const float* ln1b   = (const float*)d_in[8];
    const float* W1     = (const float*)d_in[9];
    const float* W2     = (const float*)d_in[10];
    const float* ln2g   = (const float*)d_in[11];
    const float* ln2b   = (const float*)d_in[12];
    float* out = (float*)d_out;

    #define SYM(p, s) void* p; cudaGetSymbolAddress(&p, s)
    SYM(srcp, g_src); SYM(tgtp, g_tgt);
    SYM(wqp, g_wq); SYM(wkp, g_wk); SYM(wvp, g_wv); SYM(wmp, g_wm);
    SYM(w1p, g_w1); SYM(w2p, g_w2);
    SYM(qp, g_q); SYM(kp, g_k); SYM(vtp, g_vt);
    SYM(msgp, g_msg); SYM(msgnp, g_msgn); SYM(hidp, g_hid);
    #undef SYM

    cudaFuncSetAttribute(mma_gemm128<V_PROJ>, cudaFuncAttributeMaxDynamicSharedMemorySize, G128_SMEM);
    cudaFuncSetAttribute(mma_gemm128<V_W1>,   cudaFuncAttributeMaxDynamicSharedMemorySize, G128_SMEM);
    cudaFuncSetAttribute(mma_gemm<V_WM>,      cudaFuncAttributeMaxDynamicSharedMemorySize, GEMM_SMEM);
    cudaFuncSetAttribute(mma_gemm<V_W2>,      cudaFuncAttributeMaxDynamicSharedMemorySize, GEMM_SMEM);
    cudaFuncSetAttribute(flash_kernel,        cudaFuncAttributeMaxDynamicSharedMemorySize, FLASH_SMEM);

    // merged fp32 -> fp16 conversion (single launch)
    {
        CvtP cp;
        const float* ins[8]  = {source, target, Wq, Wk, Wv, Wm, W1, W2};
        void* outs[8]        = {srcp, tgtp, wqp, wkp, wvp, wmp, w1p, w2p};
        int n2s[8] = {Mtot*Dn/2, Mtot*Dn/2, Dn*Dn/2, Dn*Dn/2, Dn*Dn/2, Dn*Dn/2,
                      DHn*2*Dn/2, Dn*DHn/2};
        int acc = 0;
        for (int j = 0; j < 8; j++) {
            cp.in[j] = (const float2*)ins[j];
            cp.out[j] = (__half2*)outs[j];
            acc += n2s[j];
            cp.end[j] = acc;
        }
        cvt_all_kernel<<<(acc + 255) / 256, 256>>>(cp);
    }

    GP p;

    // fused Q/K/V projections: z==2 writes V transposed into g_vt
    p = GP{};
    p.A  = (const __half*)srcp;
    p.A2 = (const __half*)tgtp;
    p.Bx[0] = (const __half*)wqp; p.Bx[1] = (const __half*)wkp; p.Bx[2] = (const __half*)wvp;
    p.Ox[0] = (__half*)qp;        p.Ox[1] = (__half*)kp;        p.Ox[2] = (__half*)vtp;
    p.K = Dn; p.Nout = Dn;
    mma_gemm128<V_PROJ><<<dim3(2, Mtot/128, 3), 256, G128_SMEM>>>(p);

    // fused attention
    flash_kernel<<<dim3(LWn/32, NWn), 256, FLASH_SMEM>>>(
        (const __half*)qp, (const __half*)kp, (const __half*)vtp, mask, (__half*)msgp);

    // msg @ Wm^T with fused LN1 -> fp16 msgn
    p = GP{}; p.A=(const __half*)msgp; p.B=(const __half*)wmp;
    p.lng=ln1g; p.lnb=ln1b; p.outh=(__half*)msgnp; p.K=Dn; p.Nout=Dn;
    mma_gemm<V_WM><<<dim3(1, Mtot/128), 512, GEMM_SMEM>>>(p);

    // hid = gelu([source, msg] @ W1^T)
    p = GP{}; p.A=(const __half*)srcp; p.A2=(const __half*)msgnp;
    p.B=(const __half*)w1p;
    p.outh=(__half*)hidp; p.K=2*Dn; p.Nout=DHn;
    mma_gemm128<V_W1><<<dim3(DHn/128, Mtot/128), 256, G128_SMEM>>>(p);

    // out = source + LN2(hid @ W2^T)
    p = GP{}; p.A=(const __half*)hidp; p.B=(const __half*)w2p;
    p.lng=ln2g; p.lnb=ln2b; p.resid=source; p.outf=out; p.K=DHn; p.Nout=Dn;
    mma_gemm<V_W2><<<dim3(1, Mtot/128), 512, GEMM_SMEM>>>(p);
}

// round 17
// speedup vs baseline: 1.5404x; 1.0290x over previous
#include <cuda_runtime.h>
#include <cuda_fp16.h>
#include <math.h>
#include <stdint.h>

#define Bn 8
#define HWn 4096
#define Dn 256
#define LWn 1024
#define NWn 32
#define DHn 2048
#define Mtot (Bn*HWn)

// ---------------- scratch (device globals; allocation is forbidden) --------
#define AL16 __align__(16)
__device__ AL16 __half g_src[Mtot*Dn];
__device__ AL16 __half g_tgt[Mtot*Dn];
__device__ AL16 __half g_wq[Dn*Dn], g_wk[Dn*Dn], g_wv[Dn*Dn], g_wm[Dn*Dn];
__device__ AL16 __half g_w1[DHn*2*Dn];
__device__ AL16 __half g_w2[Dn*DHn];
__device__ AL16 __half g_q[Mtot*Dn], g_k[Mtot*Dn], g_vt[Mtot*Dn];
__device__ AL16 __half g_msg[Mtot*Dn];
__device__ AL16 __half g_msgn[Mtot*Dn];
__device__ AL16 __half g_hid[(size_t)Mtot*DHn];

// ---------------- portable PTX helpers (sm_80+ class only) -----------------
__device__ __forceinline__ uint32_t smem_u32(const void* p) {
    uint32_t a;
    asm("{ .reg .u64 t; cvta.to.shared.u64 t, %1; cvt.u32.u64 %0, t; }" : "=r"(a) : "l"(p));
    return a;
}
#define SWZ(o) ((o) ^ (((o) >> 3) & 0x70))

#define CP16(dst, src) asm volatile("cp.async.cg.shared.global [%0],[%1],16;" \
    :: "r"(dst), "l"(__cvta_generic_to_global(src)) : "memory")
#define CP_COMMIT() asm volatile("cp.async.commit_group;" ::: "memory")
#define CP_WAIT1()  asm volatile("cp.async.wait_group 1;" ::: "memory")
#define CP_WAIT0()  asm volatile("cp.async.wait_group 0;" ::: "memory")

#define LDMX4(r, a) asm volatile("ldmatrix.sync.aligned.m8n8.x4.shared.b16 {%0,%1,%2,%3},[%4];" \
    : "=r"((r)[0]), "=r"((r)[1]), "=r"((r)[2]), "=r"((r)[3]) : "r"(a))

#define MMA(d, a, b) asm volatile( \
    "mma.sync.aligned.m16n8k16.row.col.f32.f16.f16.f32 " \
    "{%0,%1,%2,%3},{%4,%5,%6,%7},{%8,%9},{%0,%1,%2,%3};" \
    : "+f"((d)[0]), "+f"((d)[1]), "+f"((d)[2]), "+f"((d)[3]) \
    : "r"((a)[0]), "r"((a)[1]), "r"((a)[2]), "r"((a)[3]), "r"((b)[0]), "r"((b)[1]))

// window-token permutation: roll(-16,-16) + 2x2 window split
__device__ __forceinline__ int win_tok(int wi, int l) {
    int i = l >> 5, j = l & 31;
    int y = (((wi >> 1) << 5) + i + 16) & 63;
    int x = (((wi &  1) << 5) + j + 16) & 63;
    return (y << 6) | x;
}

// ---------------- merged fp32 -> fp16 conversion (one launch) ---------------
struct CvtP {
    const float2* in[8];
    __half2* out[8];
    int end[8];
};
__global__ void cvt_all_kernel(CvtP p)
{
    int i = blockIdx.x * 256 + threadIdx.x;
    if (i >= p.end[7]) return;
    int s = 0;
    #pragma unroll
    for (int j = 0; j < 7; j++) s += (i >= p.end[j]);
    int base = (s == 0) ? 0 : p.end[s - 1];
    p.out[s][i - base] = __float22half2_rn(p.in[s][i - base]);
}

// ======================================================================
// Flash attention v6 (FA2-style): 64 query rows/CTA, 128 threads,
// S and P entirely in registers (S-accum frag == A-operand frag after
// half2 pack). Row sums in registers. 2 CTAs/SM.
// ======================================================================
#define FQ_OFF 0                 // 64 rows x 528 B = 33792 (reused for O staging)
#define FK_OFF 33792             // 2 x 16896
#define FV_OFF 67584             // 2 x 20480
#define FA2_SMEM 108544

__global__ void __launch_bounds__(128, 2)
flash_kernel(const __half* __restrict__ q, const __half* __restrict__ k,
             const __half* __restrict__ vt, const float* __restrict__ mask,
             __half* __restrict__ msg)
{
    extern __shared__ char sm[];
    uint32_t sb = smem_u32(sm);
    const int tid = threadIdx.x, wid = tid >> 5, lane = tid & 31;
    const int m0 = blockIdx.x * 64;
    const int bw = blockIdx.y, b = bw >> 2, wi = bw & 3;
    const float* maskw = mask + (size_t)wi * LWn * LWn;

    // ---- stage Q (64 gathered rows x 256) ----
    #pragma unroll
    for (int it = 0; it < 16; it++) {
        int idx = tid + it * 128, row = idx >> 5, seg = idx & 31;
        const __half* src = q + ((size_t)b * HWn + win_tok(wi, m0 + row)) * Dn + seg * 8;
        CP16(sb + FQ_OFF + row * 528 + seg * 16, src);
    }
    CP_COMMIT(); CP_WAIT0(); __syncthreads();
    uint32_t af[16][4];
    {
        int qrow = wid * 16 + (lane & 15);
        #pragma unroll
        for (int kf = 0; kf < 16; kf++)
            LDMX4(af[kf], sb + FQ_OFF + qrow * 528 + (kf * 16 + (lane >> 4) * 8) * 2);
    }

    // ---- K/V chunk prefetch (32 keys per chunk, double-buffered) ----
    auto fillKV = [&](int ch) {
        uint32_t kbuf = sb + FK_OFF + (ch & 1) * 16896;
        uint32_t vbuf = sb + FV_OFF + (ch & 1) * 20480;
        int kc = ch * 32;
        #pragma unroll
        for (int it = 0; it < 8; it++) {
            int idx = tid + it * 128, row = idx >> 5, seg = idx & 31;
            const __half* src = k + ((size_t)b * HWn + win_tok(wi, kc + row)) * Dn + seg * 8;
            CP16(kbuf + row * 528 + seg * 16, src);
        }
        #pragma unroll
        for (int it = 0; it < 8; it++) {
            int idx = tid + it * 128, row = idx >> 3, seg = idx & 7;
            // 256 d-rows x 4 segs... idx>>3 gives 0..127; two passes over rows via seg&4
            int vrow = (idx >> 2) & 255;
            int vseg = idx & 3;
            const __half* src = vt + ((size_t)b * Dn + vrow) * (size_t)HWn + win_tok(wi, kc + vseg * 8);
            CP16(vbuf + vrow * 80 + vseg * 16, src);
            (void)row; (void)seg;
        }
        CP_COMMIT();
    };

    fillKV(0);
    float oacc[32][4];
    #pragma unroll
    for (int nb = 0; nb < 32; nb++)
        #pragma unroll
        for (int e = 0; e < 4; e++) oacc[nb][e] = 0.f;
    float srun0 = 0.f, srun1 = 0.f;
    const int r0 = lane >> 2;
    const int grow0 = m0 + wid * 16 + r0;

    for (int ch = 0; ch < 32; ch++) {
        if (ch + 1 < 32) { fillKV(ch + 1); CP_WAIT1(); } else CP_WAIT0();
        __syncthreads();
        uint32_t kbuf = sb + FK_OFF + (ch & 1) * 16896;
        uint32_t vbuf = sb + FV_OFF + (ch & 1) * 20480;
        int kc = ch * 32;

        // mask prefetch (overlaps S MMAs)
        float2 mk[4][2];
        #pragma unroll
        for (int j = 0; j < 4; j++) {
            int col = kc + j * 8 + (lane & 3) * 2;
            mk[j][0] = *(const float2*)&maskw[(size_t)grow0 * LWn + col];
            mk[j][1] = *(const float2*)&maskw[(size_t)(grow0 + 8) * LWn + col];
        }

        // ---- S = Q·K^T (16 rows x 32 keys per warp) ----
        float sac[4][4];
        #pragma unroll
        for (int j = 0; j < 4; j++)
            #pragma unroll
            for (int e = 0; e < 4; e++) sac[j][e] = 0.f;
        #pragma unroll
        for (int kf = 0; kf < 16; kf++) {
            uint32_t t4[4];
            #pragma unroll
            for (int jj = 0; jj < 2; jj++) {
                LDMX4(t4, kbuf + (jj * 16 + (lane & 15)) * 528 + (kf * 16 + (lane >> 4) * 8) * 2);
                uint32_t b0[2] = {t4[0], t4[2]}, b1[2] = {t4[1], t4[3]};
                MMA(sac[jj * 2],     af[kf], b0);
                MMA(sac[jj * 2 + 1], af[kf], b1);
            }
        }

        // ---- P = exp(s - 2), pack to A-frags, accumulate row sums ----
        uint32_t pA[2][4];
        #pragma unroll
        for (int j = 0; j < 4; j++) {
            float p0 = exp2f(fmaf(sac[j][0] * 0.0625f + mk[j][0].x, 1.4426950408889634f, -2.8853900817779268f));
            float p1 = exp2f(fmaf(sac[j][1] * 0.0625f + mk[j][0].y, 1.4426950408889634f, -2.8853900817779268f));
            float p2 = exp2f(fmaf(sac[j][2] * 0.0625f + mk[j][1].x, 1.4426950408889634f, -2.8853900817779268f));
            float p3 = exp2f(fmaf(sac[j][3] * 0.0625f + mk[j][1].y, 1.4426950408889634f, -2.8853900817779268f));
            srun0 += p0 + p1;
            srun1 += p2 + p3;
            __half2 h01 = __floats2half2_rn(p0, p1);
            __half2 h23 = __floats2half2_rn(p2, p3);
            pA[j >> 1][(j & 1) * 2]     = *(uint32_t*)&h01;
            pA[j >> 1][(j & 1) * 2 + 1] = *(uint32_t*)&h23;
        }

        // ---- O += P·V ----
        #pragma unroll
        for (int kf2 = 0; kf2 < 2; kf2++) {
            #pragma unroll
            for (int g = 0; g < 16; g++) {
                uint32_t t4[4];
                int brow = g * 16 + ((lane >> 4) << 3) + (lane & 7);
                LDMX4(t4, vbuf + brow * 80 + (kf2 * 16 + ((lane >> 3) & 1) * 8) * 2);
                uint32_t b0[2] = {t4[0], t4[1]}, b1[2] = {t4[2], t4[3]};
                MMA(oacc[g * 2],     pA[kf2], b0);
                MMA(oacc[g * 2 + 1], pA[kf2], b1);
            }
        }
        __syncthreads();
    }

    // ---- row sums: reduce over the 4 lanes sharing a row ----
    #pragma unroll
    for (int off = 1; off <= 2; off <<= 1) {
        srun0 += __shfl_xor_sync(0xffffffff, srun0, off);
        srun1 += __shfl_xor_sync(0xffffffff, srun1, off);
    }
    float is0 = 1.f / srun0, is1 = 1.f / srun1;

    // ---- stage O to smem (reuse Q region), scatter via win_tok ----
    __syncthreads();
    {
        int row = wid * 16 + r0;
        #pragma unroll
        for (int nb = 0; nb < 32; nb++) {
            int col = nb * 8 + (lane & 3) * 2;
            __half2 h0 = __floats2half2_rn(oacc[nb][0] * is0, oacc[nb][1] * is0);
            __half2 h1 = __floats2half2_rn(oacc[nb][2] * is1, oacc[nb][3] * is1);
            *(uint32_t*)(sm + (row * 264 + col) * 2)       = *(uint32_t*)&h0;
            *(uint32_t*)(sm + ((row + 8) * 264 + col) * 2) = *(uint32_t*)&h1;
        }
    }
    __syncthreads();
    #pragma unroll
    for (int it = 0; it < 16; it++) {
        int idx = tid + it * 128;
        int row = idx >> 5, c4 = idx & 31;          // c4: 8-half (16B) group
        uint4 val = *(uint4*)(sm + (row * 264 + c4 * 8) * 2);
        *(uint4*)(msg + ((size_t)b * HWn + win_tok(wi, m0 + row)) * Dn + c4 * 8) = val;
    }
}

// ======================================================================
// GEMM-128 (unchanged): PROJ (z==2 writes V^T) and W1.
// ======================================================================
#define V_PROJ 0
#define V_WM   3
#define V_W1   4
#define V_W2   5

struct GP {
    const __half *A, *B;
    const __half *A2;
    const __half *Bx[3];
    __half *Ox[3];
    const float *resid, *lng, *lnb;
    float *outf;
    __half *outh;
    int K, Nout;
};

#define TILE128 16384
#define STG128  (2*TILE128)
#define G128_SMEM (3*STG128 + 1024)

template<int V>
__global__ void __launch_bounds__(256, 2)
mma_gemm128(GP p)
{
    extern __shared__ char smraw[];
    char* sm = (char*)((((uintptr_t)smraw) + 1023) & ~(uintptr_t)1023);
    uint32_t sb = smem_u32(sm);

    const int tid = threadIdx.x, wid = tid >> 5, lane = tid & 31;
    const int wm = (wid >> 1) * 32;
    const int wn = (wid & 1) * 64;

    const int n0 = blockIdx.x * 128;
    const int m0 = blockIdx.y * 128;
    const int KTOT = p.K, NCH = KTOT >> 6;

    const __half* Aptr = p.A;
    const __half* Bptr = p.B;
    __half* outh = p.outh;
    if constexpr (V == V_PROJ) {
        Aptr = blockIdx.z ? p.A2 : p.A;
        Bptr = p.Bx[blockIdx.z];
        outh = p.Ox[blockIdx.z];
    }

    float acc[2][8][4];
    #pragma unroll
    for (int i = 0; i < 2; i++)
        #pragma unroll
        for (int j = 0; j < 8; j++)
            #pragma unroll
            for (int e = 0; e < 4; e++) acc[i][j][e] = 0.f;

    auto fill = [&](int c) {
        uint32_t bb = sb + (c % 3) * STG128;
        int k0 = c << 6;
        #pragma unroll
        for (int it = 0; it < 4; it++) {
            int idx = tid + it * 256;
            int r = idx >> 3, qq = idx & 7;
            uint32_t o = SWZ((uint32_t)(r * 128 + qq * 16));
            const __half *pa;
            if constexpr (V == V_W1) {
                size_t row = (size_t)(m0 + r);
                pa = (k0 < 256) ? p.A + row * 256 + k0 + qq * 8
                                : p.A2 + row * 256 + (k0 - 256) + qq * 8;
            } else {
                pa = Aptr + (size_t)(m0 + r) * (size_t)KTOT + k0 + qq * 8;
            }
            CP16(bb + o, pa);
        }
        #pragma unroll
        for (int it = 0; it < 4; it++) {
            int idx = tid + it * 256;
            int r = idx >> 3, qq = idx & 7;
            uint32_t o = SWZ((uint32_t)(r * 128 + qq * 16));
            CP16(bb + TILE128 + o, Bptr + (size_t)(n0 + r) * (size_t)KTOT + k0 + qq * 8);
        }
        CP_COMMIT();
    };

    fill(0);
    if (NCH > 1) fill(1);
    for (int c = 0; c < NCH; c++) {
        if (c + 1 < NCH) CP_WAIT1(); else CP_WAIT0();
        __syncthreads();
        if (c + 2 < NCH) fill(c + 2);
        uint32_t bb = sb + (c % 3) * STG128;
        const uint32_t tA = bb, tB = bb + TILE128;
        #pragma unroll
        for (int kk = 0; kk < 4; kk++) {
            uint32_t afr[2][4];
            int arow = wm + (lane & 15);
            int acol = kk * 16 + (lane >> 4) * 8;
            #pragma unroll
            for (int mf = 0; mf < 2; mf++)
                LDMX4(afr[mf], tA + SWZ((uint32_t)((arow + mf * 16) * 128 + acol * 2)));
            int brow0 = wn + ((lane >> 4) << 3) + (lane & 7);
            int bcol = kk * 16 + ((lane >> 3) & 1) * 8;
            #pragma unroll
            for (int np = 0; np < 4; np++) {
                uint32_t t4[4];
                LDMX4(t4, tB + SWZ((uint32_t)((brow0 + np * 16) * 128 + bcol * 2)));
                uint32_t b0[2] = {t4[0], t4[1]}, b1[2] = {t4[2], t4[3]};
                #pragma unroll
                for (int mf = 0; mf < 2; mf++) {
                    MMA(acc[mf][np * 2],     afr[mf], b0);
                    MMA(acc[mf][np * 2 + 1], afr[mf], b1);
                }
            }
        }
        __syncthreads();
    }

    float* stg = (float*)sm;
    #pragma unroll
    for (int mf = 0; mf < 2; mf++)
        #pragma unroll
        for (int nf = 0; nf < 8; nf++) {
            int r0 = wm + mf * 16 + (lane >> 2);
            int c0 = wn + nf * 8 + (lane & 3) * 2;
            stg[r0 * 130 + c0]     = acc[mf][nf][0];
            stg[r0 * 130 + c0 + 1] = acc[mf][nf][1];
            stg[(r0 + 8) * 130 + c0]     = acc[mf][nf][2];
            stg[(r0 + 8) * 130 + c0 + 1] = acc[mf][nf][3];
        }
    __syncthreads();

    if constexpr (V == V_PROJ) {
        if (blockIdx.z == 2) {
            int bb2 = m0 >> 12, t0 = m0 & (HWn - 1);
            #pragma unroll
            for (int it = 0; it < 32; it++) {
                int e = tid + it * 256;
                int col = e >> 6, rp = e & 63;
                float v0 = stg[(2 * rp) * 130 + col];
                float v1 = stg[(2 * rp + 1) * 130 + col];
                __half2 h = __floats2half2_rn(v0, v1);
                *(__half2*)(outh + ((size_t)(bb2 * Dn + n0 + col)) * HWn + t0 + 2 * rp) = h;
            }
            return;
        }
    }
    #pragma unroll
    for (int it = 0; it < 16; it++) {
        int e = tid + it * 256;
        int row = e >> 5;
        int c4 = (e & 31) << 2;
        float4 v = make_float4(stg[row*130+c4], stg[row*130+c4+1],
                               stg[row*130+c4+2], stg[row*130+c4+3]);
        if constexpr (V == V_W1) {
            v.x = 0.5f * v.x * (1.f + erff(v.x * 0.70710678118654752f));
            v.y = 0.5f * v.y * (1.f + erff(v.y * 0.70710678118654752f));
            v.z = 0.5f * v.z * (1.f + erff(v.z * 0.70710678118654752f));
            v.w = 0.5f * v.w * (1.f + erff(v.w * 0.70710678118654752f));
        }
        size_t gi = (size_t)(m0 + row) * (size_t)p.Nout + n0 + c4;
        __half2* ph = (__half2*)(outh + gi);
        ph[0] = __floats2half2_rn(v.x, v.y);
        ph[1] = __floats2half2_rn(v.z, v.w);
    }
}

// ---------------- GEMM-256 (unchanged from R16): reg-LN epilogue ----------
#define ASIZE 16384
#define BSIZE 32768
#define STAGE (ASIZE+BSIZE)
#define SSTR  260
#define OFF_GB   133120
#define OFF_RED  135168
#define OFF_MUSD 139264
#define GEMM_SMEM (3*STAGE + 1024)

template<int V>
__global__ void __launch_bounds__(512)
mma_gemm(GP p)
{
    extern __shared__ char smraw[];
    char* sm = (char*)((((uintptr_t)smraw) + 1023) & ~(uintptr_t)1023);
    uint32_t sb = smem_u32(sm);

    const int tid = threadIdx.x, wid = tid >> 5, lane = tid & 31;
    const int wm = (wid >> 2) * 32;
    const int wn = (wid & 3) * 64;

    const int n0 = blockIdx.x * 256;
    const int m0 = blockIdx.y * 128;
    const int KTOT = p.K, NCH = KTOT >> 6;

    float acc[2][8][4];
    #pragma unroll
    for (int i = 0; i < 2; i++)
        #pragma unroll
        for (int j = 0; j < 8; j++)
            #pragma unroll
            for (int e = 0; e < 4; e++) acc[i][j][e] = 0.f;

    auto fill = [&](int c) {
        uint32_t bb = sb + (c % 3) * STAGE;
        int k0 = c << 6;
        #pragma unroll
        for (int it = 0; it < 2; it++) {
            int idx = tid + it * 512;
            int r = idx >> 3, qq = idx & 7;
            uint32_t o = SWZ((uint32_t)(r * 128 + qq * 16));
            CP16(bb + o, p.A + (size_t)(m0 + r) * (size_t)KTOT + k0 + qq * 8);
        }
        #pragma unroll
        for (int it = 0; it < 4; it++) {
            int idx = tid + it * 512;
            int r = idx >> 3, qq = idx & 7;
            uint32_t o = SWZ((uint32_t)(r * 128 + qq * 16));
            CP16(bb + ASIZE + o, p.B + (size_t)(n0 + r) * (size_t)KTOT + k0 + qq * 8);
        }
        CP_COMMIT();
    };

    fill(0);
    if (NCH > 1) fill(1);
    for (int c = 0; c < NCH; c++) {
        if (c + 1 < NCH) CP_WAIT1(); else CP_WAIT0();
        __syncthreads();
        if (c + 2 < NCH) fill(c + 2);
        uint32_t bb = sb + (c % 3) * STAGE;
        const uint32_t tA = bb, tB = bb + ASIZE;
        #pragma unroll
        for (int kk = 0; kk < 4; kk++) {
            uint32_t afr[2][4];
            int arow = wm + (lane & 15);
            int acol = kk * 16 + (lane >> 4) * 8;
            #pragma unroll
            for (int mf = 0; mf < 2; mf++)
                LDMX4(afr[mf], tA + SWZ((uint32_t)((arow + mf * 16) * 128 + acol * 2)));
            int brow0 = wn + ((lane >> 4) << 3) + (lane & 7);
            int bcol = kk * 16 + ((lane >> 3) & 1) * 8;
            #pragma unroll
            for (int np = 0; np < 4; np++) {
                uint32_t t4[4];
                LDMX4(t4, tB + SWZ((uint32_t)((brow0 + np * 16) * 128 + bcol * 2)));
                uint32_t b0[2] = {t4[0], t4[1]}, b1[2] = {t4[2], t4[3]};
                #pragma unroll
                for (int mf = 0; mf < 2; mf++) {
                    MMA(acc[mf][np * 2],     afr[mf], b0);
                    MMA(acc[mf][np * 2 + 1], afr[mf], b1);
                }
            }
        }
        __syncthreads();
    }

    float* stg  = (float*)sm;
    float* gb   = (float*)(sm + OFF_GB);
    float* red1 = (float*)(sm + OFF_RED);
    float* red2 = red1 + 512;
    float2* musd = (float2*)(sm + OFF_MUSD);

    gb[tid & 511] = (tid < 256) ? p.lng[tid] : p.lnb[tid - 256];

    float s1r[4] = {}, s2r[4] = {};
    #pragma unroll
    for (int mf = 0; mf < 2; mf++)
        #pragma unroll
        for (int nf = 0; nf < 8; nf++) {
            float a0 = acc[mf][nf][0], a1 = acc[mf][nf][1];
            float a2 = acc[mf][nf][2], a3 = acc[mf][nf][3];
            s1r[mf*2]   += a0 + a1;   s2r[mf*2]   += a0*a0 + a1*a1;
            s1r[mf*2+1] += a2 + a3;   s2r[mf*2+1] += a2*a2 + a3*a3;
        }
    #pragma unroll
    for (int off = 1; off <= 2; off <<= 1)
        #pragma unroll
        for (int i = 0; i < 4; i++) {
            s1r[i] += __shfl_xor_sync(0xffffffff, s1r[i], off);
            s2r[i] += __shfl_xor_sync(0xffffffff, s2r[i], off);
        }
    if ((lane & 3) == 0) {
        int wgn = wid & 3;
        #pragma unroll
        for (int i = 0; i < 4; i++) {
            int row = wm + (i >> 1) * 16 + (i & 1) * 8 + (lane >> 2);
            red1[wgn * 128 + row] = s1r[i];
            red2[wgn * 128 + row] = s2r[i];
        }
    }

    #pragma unroll
    for (int mf = 0; mf < 2; mf++)
        #pragma unroll
        for (int nf = 0; nf < 8; nf++) {
            int r0 = wm + mf * 16 + (lane >> 2);
            int c0 = wn + nf * 8 + (lane & 3) * 2;
            stg[r0 * SSTR + c0]     = acc[mf][nf][0];
            stg[r0 * SSTR + c0 + 1] = acc[mf][nf][1];
            stg[(r0 + 8) * SSTR + c0]     = acc[mf][nf][2];
            stg[(r0 + 8) * SSTR + c0 + 1] = acc[mf][nf][3];
        }
    __syncthreads();

    if (tid < 128) {
        float s1 = red1[tid] + red1[128 + tid] + red1[256 + tid] + red1[384 + tid];
        float s2 = red2[tid] + red2[128 + tid] + red2[256 + tid] + red2[384 + tid];
        float mu = s1 * (1.f / 256.f);
        float rstd = rsqrtf(s2 * (1.f / 256.f) - mu * mu + 1e-5f);
        musd[tid] = make_float2(mu, rstd);
    }
    __syncthreads();

    #pragma unroll
    for (int it = 0; it < 16; it++) {
        int e = tid + it * 512;
        int row = e >> 6;
        int c4 = (e & 63) << 2;
        float4 v = *(float4*)&stg[row * SSTR + c4];
        float2 ms = musd[row];
        float4 g4 = *(float4*)&gb[c4];
        float4 b4 = *(float4*)&gb[256 + c4];
        v.x = (v.x - ms.x) * ms.y * g4.x + b4.x;
        v.y = (v.y - ms.x) * ms.y * g4.y + b4.y;
        v.z = (v.z - ms.x) * ms.y * g4.z + b4.z;
        v.w = (v.w - ms.x) * ms.y * g4.w + b4.w;
        size_t gi = (size_t)(m0 + row) * 256 + c4;
        if constexpr (V == V_WM) {
            __half2* ph = (__half2*)(p.outh + gi);
            ph[0] = __floats2half2_rn(v.x, v.y);
            ph[1] = __floats2half2_rn(v.z, v.w);
        } else {
            float4 rs = *(const float4*)&p.resid[gi];
            v.x += rs.x; v.y += rs.y; v.z += rs.z; v.w += rs.w;
            *(float4*)&p.outf[gi] = v;
        }
    }
}

// ---------------- host -------------------------------------------------------
extern "C" void kernel_launch(void* const* d_in, const int* in_sizes, int n_in,
                              void* d_out, int out_size)
{
    const float* source = (const float*)d_in[0];
    const float* target = (const float*)d_in[1];
    const float* mask   = (const float*)d_in[2];
    const float* Wq     = (const float*)d_in[3];
    const float* Wk     = (const float*)d_in[4];
    const float* Wv     = (const float*)d_in[5];
    const float* Wm     = (const float*)d_in[6];
    const float* ln1g   = (const float*)d_in[7];
    const float* ln1b   = (const float*)d_in[8];
    const float* W1     = (const float*)d_in[9];
    const float* W2     = (const float*)d_in[10];
    const float* ln2g   = (const float*)d_in[11];
    const float* ln2b   = (const float*)d_in[12];
    float* out = (float*)d_out;

    #define SYM(p, s) void* p; cudaGetSymbolAddress(&p, s)
    SYM(srcp, g_src); SYM(tgtp, g_tgt);
    SYM(wqp, g_wq); SYM(wkp, g_wk); SYM(wvp, g_wv); SYM(wmp, g_wm);
    SYM(w1p, g_w1); SYM(w2p, g_w2);
    SYM(qp, g_q); SYM(kp, g_k); SYM(vtp, g_vt);
    SYM(msgp, g_msg); SYM(msgnp, g_msgn); SYM(hidp, g_hid);
    #undef SYM

    cudaFuncSetAttribute(mma_gemm128<V_PROJ>, cudaFuncAttributeMaxDynamicSharedMemorySize, G128_SMEM);
    cudaFuncSetAttribute(mma_gemm128<V_W1>,   cudaFuncAttributeMaxDynamicSharedMemorySize, G128_SMEM);
    cudaFuncSetAttribute(mma_gemm<V_WM>,      cudaFuncAttributeMaxDynamicSharedMemorySize, GEMM_SMEM);
    cudaFuncSetAttribute(mma_gemm<V_W2>,      cudaFuncAttributeMaxDynamicSharedMemorySize, GEMM_SMEM);
    cudaFuncSetAttribute(flash_kernel,        cudaFuncAttributeMaxDynamicSharedMemorySize, FA2_SMEM);

    // merged fp32 -> fp16 conversion (single launch)
    {
        CvtP cp;
        const float* ins[8]  = {source, target, Wq, Wk, Wv, Wm, W1, W2};
        void* outs[8]        = {srcp, tgtp, wqp, wkp, wvp, wmp, w1p, w2p};
        int n2s[8] = {Mtot*Dn/2, Mtot*Dn/2, Dn*Dn/2, Dn*Dn/2, Dn*Dn/2, Dn*Dn/2,
                      DHn*2*Dn/2, Dn*DHn/2};
        int acc = 0;
        for (int j = 0; j < 8; j++) {
            cp.in[j] = (const float2*)ins[j];
            cp.out[j] = (__half2*)outs[j];
            acc += n2s[j];
            cp.end[j] = acc;
        }
        cvt_all_kernel<<<(acc + 255) / 256, 256>>>(cp);
    }

    GP p;

    // fused Q/K/V projections: z==2 writes V transposed into g_vt
    p = GP{};
    p.A  = (const __half*)srcp;
    p.A2 = (const __half*)tgtp;
    p.Bx[0] = (const __half*)wqp; p.Bx[1] = (const __half*)wkp; p.Bx[2] = (const __half*)wvp;
    p.Ox[0] = (__half*)qp;        p.Ox[1] = (__half*)kp;        p.Ox[2] = (__half*)vtp;
    p.K = Dn; p.Nout = Dn;
    mma_gemm128<V_PROJ><<<dim3(2, Mtot/128, 3), 256, G128_SMEM>>>(p);

    // fused attention (FA2: register-resident P, 64 rows/CTA)
    flash_kernel<<<dim3(LWn/64, NWn), 128, FA2_SMEM>>>(
        (const __half*)qp, (const __half*)kp, (const __half*)vtp, mask, (__half*)msgp);

    // msg @ Wm^T with fused LN1 -> fp16 msgn
    p = GP{}; p.A=(const __half*)msgp; p.B=(const __half*)wmp;
    p.lng=ln1g; p.lnb=ln1b; p.outh=(__half*)msgnp; p.K=Dn; p.Nout=Dn;
    mma_gemm<V_WM><<<dim3(1, Mtot/128), 512, GEMM_SMEM>>>(p);

    // hid = gelu([source, msg] @ W1^T)
    p = GP{}; p.A=(const __half*)srcp; p.A2=(const __half*)msgnp;
    p.B=(const __half*)w1p;
    p.outh=(__half*)hidp; p.K=2*Dn; p.Nout=DHn;
    mma_gemm128<V_W1><<<dim3(DHn/128, Mtot/128), 256, G128_SMEM>>>(p);

    // out = source + LN2(hid @ W2^T)
    p = GP{}; p.A=(const __half*)hidp; p.B=(const __half*)w2p;
    p.lng=ln2g; p.lnb=ln2b; p.resid=source; p.outf=out; p.K=DHn; p.Nout=Dn;
    mma_gemm<V_W2><<<dim3(1, Mtot/128), 512, GEMM_SMEM>>>(p);
}